// round 14
// baseline (speedup 1.0000x reference)
#include <cuda_runtime.h>
#include <cuda_fp16.h>
#include <math.h>

#define NMAX 50000
#define EMAX 800000
#define N2MAX (2 * NMAX)
#define E2MAX (2 * EMAX)

// ---------------- scratch (static device globals; no allocation) ------------
__device__ __half g_bufA[N2MAX * 128];   // GEMM outputs (pre-agg), fp16
__device__ __half g_bufB[N2MAX * 128];   // agg1 output / projector hidden, fp16
__device__ __half g_bufC[N2MAX * 64];    // encoder output Z, fp16
__device__ float  g_dinv[N2MAX];
__device__ int    g_deg[N2MAX];
__device__ int    g_off[N2MAX + 1];
__device__ int    g_rank[E2MAX];       // per-edge slot within target node
__device__ int    g_csr[E2MAX];
__device__ int    g_bsum[128];
__device__ int    g_bpre[128];
__device__ float  g_wcomb[64 * 128];   // [Wp1 | Wc1]
__device__ float  g_bcomb[128];        // [bp1 | bc1]

// ---------------- fp16 helpers ----------------------------------------------
__device__ __forceinline__ float4 ld_half4(const __half* p) {
    uint2 r = *reinterpret_cast<const uint2*>(p);
    __half2 h0 = *reinterpret_cast<__half2*>(&r.x);
    __half2 h1 = *reinterpret_cast<__half2*>(&r.y);
    float2 f0 = __half22float2(h0), f1 = __half22float2(h1);
    return make_float4(f0.x, f0.y, f1.x, f1.y);
}
__device__ __forceinline__ void st_half4(__half* p, float4 v) {
    __half2 h0 = __floats2half2_rn(v.x, v.y);
    __half2 h1 = __floats2half2_rn(v.z, v.w);
    uint2 r;
    r.x = *reinterpret_cast<unsigned*>(&h0);
    r.y = *reinterpret_cast<unsigned*>(&h1);
    *reinterpret_cast<uint2*>(p) = r;
}
__device__ __forceinline__ unsigned pack_half2(float a, float b) {
    __half2 h = __floats2half2_rn(a, b);
    return *reinterpret_cast<unsigned*>(&h);
}

// ---------------- preprocessing head: zero deg + weight concat ---------------
__global__ void zero_pre_kernel(int n2, const float* __restrict__ Wp1,
                                const float* __restrict__ Wc1,
                                const float* __restrict__ bp1,
                                const float* __restrict__ bc1) {
    int i = blockIdx.x * blockDim.x + threadIdx.x;
    if (i < n2) g_deg[i] = 0;
    if (i < 64 * 128) {
        int k = i >> 7, n = i & 127;
        g_wcomb[i] = (n < 64) ? Wp1[k * 64 + n] : Wc1[k * 64 + n - 64];
    }
    if (i < 128) g_bcomb[i] = (i < 64) ? bp1[i] : bc1[i - 64];
}

// Histogram + per-edge rank record (one atomic per edge, rank reused by fill)
__global__ void hist_kernel(const int* __restrict__ ei1, const int* __restrict__ ei2,
                            int E, int N) {
    int i = blockIdx.x * blockDim.x + threadIdx.x;
    if (i >= 2 * E) return;
    int g = (i >= E);
    int e = i - g * E;
    const int* ei = g ? ei2 : ei1;
    int c = ei[E + e];
    g_rank[i] = atomicAdd(&g_deg[g * N + c], 1);
}

__global__ void scan_blocks_kernel(int n2) {
    int b = blockIdx.x, tid = threadIdx.x;
    int i = b * 1024 + tid;
    int lane = tid & 31, w = tid >> 5;
    int v = (i < n2) ? g_deg[i] : 0;
    int s = v;
#pragma unroll
    for (int o = 1; o < 32; o <<= 1) {
        int t = __shfl_up_sync(0xffffffffu, s, o);
        if (lane >= o) s += t;
    }
    __shared__ int wsum[32];
    if (lane == 31) wsum[w] = s;
    __syncthreads();
    if (w == 0) {
        int t = wsum[lane];
#pragma unroll
        for (int o = 1; o < 32; o <<= 1) {
            int u = __shfl_up_sync(0xffffffffu, t, o);
            if (lane >= o) t += u;
        }
        wsum[lane] = t;
    }
    __syncthreads();
    int excl = s - v + (w > 0 ? wsum[w - 1] : 0);
    if (i < n2) {
        g_off[i] = excl;
        g_dinv[i] = rsqrtf((float)(v + 1));
    }
    if (tid == 0) g_bsum[b] = wsum[31];
}

__global__ void scan_top_kernel(int nb, int n2) {
    int tid = threadIdx.x;   // 128
    __shared__ int sh[128];
    int v = (tid < nb) ? g_bsum[tid] : 0;
    sh[tid] = v;
    __syncthreads();
#pragma unroll
    for (int d = 1; d < 128; d <<= 1) {
        int t = (tid >= d) ? sh[tid - d] : 0;
        __syncthreads();
        sh[tid] += t;
        __syncthreads();
    }
    if (tid < nb) g_bpre[tid] = sh[tid] - v;
    if (tid == 127) g_off[n2] = sh[127];
}

__global__ void scan_add_kernel(int n2) {
    int i = blockIdx.x * blockDim.x + threadIdx.x;
    if (i < n2) g_off[i] += g_bpre[i >> 10];
}

// Atomic-free CSR fill using precomputed ranks
__global__ void fill_csr_kernel(const int* __restrict__ ei1, const int* __restrict__ ei2,
                                int E, int N) {
    int i = blockIdx.x * blockDim.x + threadIdx.x;
    if (i >= 2 * E) return;
    int g = (i >= E);
    int e = i - g * E;
    const int* ei = g ? ei2 : ei1;
    int r = ei[e];
    int c = ei[E + e];
    g_csr[g_off[g * N + c] + g_rank[i]] = g * N + r;
}

// ---------------- neighbor aggregation: warp per node, fp16 rows --------------
// node range [base, nodeEnd). out[n] = relu(dinv[n]*(dinv[n]*G[n]+sum dj*G[j])+b)
template <int F>
__global__ void agg_warp_kernel(const __half* __restrict__ G,
                                const float* __restrict__ bias,
                                __half* __restrict__ out, int base, int nodeEnd) {
    int node = base + blockIdx.x * (blockDim.x >> 5) + (threadIdx.x >> 5);
    if (node >= nodeEnd) return;
    int lane = threadIdx.x & 31;
    int s = g_off[node], e = g_off[node + 1];
    float dn = g_dinv[node];

    if constexpr (F == 128) {
        float4 self = ld_half4(&G[(size_t)node * F + lane * 4]);
        float4 acc = make_float4(dn * self.x, dn * self.y, dn * self.z, dn * self.w);
        int j = s;
        for (; j + 4 <= e; j += 4) {
            int n0 = g_csr[j], n1 = g_csr[j + 1], n2 = g_csr[j + 2], n3 = g_csr[j + 3];
            float d0 = g_dinv[n0], d1 = g_dinv[n1], d2 = g_dinv[n2], d3 = g_dinv[n3];
            float4 v0 = ld_half4(&G[(size_t)n0 * F + lane * 4]);
            float4 v1 = ld_half4(&G[(size_t)n1 * F + lane * 4]);
            float4 v2 = ld_half4(&G[(size_t)n2 * F + lane * 4]);
            float4 v3 = ld_half4(&G[(size_t)n3 * F + lane * 4]);
            acc.x += d0 * v0.x + d1 * v1.x + d2 * v2.x + d3 * v3.x;
            acc.y += d0 * v0.y + d1 * v1.y + d2 * v2.y + d3 * v3.y;
            acc.z += d0 * v0.z + d1 * v1.z + d2 * v2.z + d3 * v3.z;
            acc.w += d0 * v0.w + d1 * v1.w + d2 * v2.w + d3 * v3.w;
        }
        for (; j < e; j++) {
            int nj = g_csr[j];
            float dj = g_dinv[nj];
            float4 v = ld_half4(&G[(size_t)nj * F + lane * 4]);
            acc.x = fmaf(dj, v.x, acc.x); acc.y = fmaf(dj, v.y, acc.y);
            acc.z = fmaf(dj, v.z, acc.z); acc.w = fmaf(dj, v.w, acc.w);
        }
        float4 bb = *reinterpret_cast<const float4*>(&bias[lane * 4]);
        float4 o;
        o.x = fmaxf(fmaf(dn, acc.x, bb.x), 0.f);
        o.y = fmaxf(fmaf(dn, acc.y, bb.y), 0.f);
        o.z = fmaxf(fmaf(dn, acc.z, bb.z), 0.f);
        o.w = fmaxf(fmaf(dn, acc.w, bb.w), 0.f);
        st_half4(&out[(size_t)node * F + lane * 4], o);
    } else {
        float2 self = __half22float2(*reinterpret_cast<const __half2*>(&G[(size_t)node * F + lane * 2]));
        float2 acc = make_float2(dn * self.x, dn * self.y);
        int j = s;
        for (; j + 4 <= e; j += 4) {
            int n0 = g_csr[j], n1 = g_csr[j + 1], n2 = g_csr[j + 2], n3 = g_csr[j + 3];
            float d0 = g_dinv[n0], d1 = g_dinv[n1], d2 = g_dinv[n2], d3 = g_dinv[n3];
            float2 v0 = __half22float2(*reinterpret_cast<const __half2*>(&G[(size_t)n0 * F + lane * 2]));
            float2 v1 = __half22float2(*reinterpret_cast<const __half2*>(&G[(size_t)n1 * F + lane * 2]));
            float2 v2 = __half22float2(*reinterpret_cast<const __half2*>(&G[(size_t)n2 * F + lane * 2]));
            float2 v3 = __half22float2(*reinterpret_cast<const __half2*>(&G[(size_t)n3 * F + lane * 2]));
            acc.x += d0 * v0.x + d1 * v1.x + d2 * v2.x + d3 * v3.x;
            acc.y += d0 * v0.y + d1 * v1.y + d2 * v2.y + d3 * v3.y;
        }
        for (; j < e; j++) {
            int nj = g_csr[j];
            float dj = g_dinv[nj];
            float2 v = __half22float2(*reinterpret_cast<const __half2*>(&G[(size_t)nj * F + lane * 2]));
            acc.x = fmaf(dj, v.x, acc.x); acc.y = fmaf(dj, v.y, acc.y);
        }
        float2 bb = *reinterpret_cast<const float2*>(&bias[lane * 2]);
        float ox = fmaxf(fmaf(dn, acc.x, bb.x), 0.f);
        float oy = fmaxf(fmaf(dn, acc.y, bb.y), 0.f);
        *reinterpret_cast<__half2*>(&out[(size_t)node * F + lane * 2]) =
            __floats2half2_rn(ox, oy);
    }
}

// ---------------- FP16 tensor-core GEMM (m16n8k16, fp32 accumulate) ----------
__device__ __forceinline__ void mma_f16(float c[4], const unsigned a[4],
                                        const unsigned b[2]) {
    asm volatile(
        "mma.sync.aligned.m16n8k16.row.col.f32.f16.f16.f32 "
        "{%0,%1,%2,%3}, {%4,%5,%6,%7}, {%8,%9}, {%0,%1,%2,%3};"
        : "+f"(c[0]), "+f"(c[1]), "+f"(c[2]), "+f"(c[3])
        : "r"(a[0]), "r"(a[1]), "r"(a[2]), "r"(a[3]), "r"(b[0]), "r"(b[1]));
}

// Proven round-10 GEMM core.
// EPI 3: out = l2norm_row(acc + vec[col])   (F==128, CT=float)
// EPI 4: out = acc (raw store)
template <int K, int F, int EPI, int LDA, typename AT, typename CT>
__device__ __forceinline__ void gemm_block(
    const AT* __restrict__ A, const float* __restrict__ B,
    const float* __restrict__ vec, CT* __restrict__ C,
    int rowBase, int nRows) {
    constexpr int BK = 32;
    constexpr int SST = 20;
    constexpr int WN = F / 32;
    constexpr int THREADS = 32 * 2 * WN;
    __shared__ unsigned As2[128 * SST];
    __shared__ unsigned Bs2[F * SST];

    int tid = threadIdx.x;
    int lane = tid & 31;
    int warp = tid >> 5;
    int warpM = warp / WN;
    int warpN = warp % WN;

    float acc[4][4][4];
#pragma unroll
    for (int i = 0; i < 4; i++)
#pragma unroll
        for (int j = 0; j < 4; j++)
#pragma unroll
            for (int q = 0; q < 4; q++) acc[i][j][q] = 0.0f;

    for (int kc = 0; kc < K; kc += BK) {
        constexpr int AQ = (128 * BK / 4) / THREADS;
#pragma unroll
        for (int q = 0; q < AQ; q++) {
            int lin = tid + q * THREADS;
            int r = lin >> 3;
            int k4 = lin & 7;
            unsigned p0 = 0, p1 = 0;
            int gr = rowBase + r;
            if (gr < nRows) {
                if constexpr (sizeof(AT) == 4) {
                    float4 v = *reinterpret_cast<const float4*>(
                        &A[(size_t)gr * LDA + kc + k4 * 4]);
                    p0 = pack_half2(v.x, v.y);
                    p1 = pack_half2(v.z, v.w);
                } else {
                    uint2 v = *reinterpret_cast<const uint2*>(
                        &A[(size_t)gr * LDA + kc + k4 * 4]);
                    p0 = v.x; p1 = v.y;
                }
            }
            As2[r * SST + k4 * 2 + 0] = p0;
            As2[r * SST + k4 * 2 + 1] = p1;
        }
        {
            int n = tid % F;
            int kg = tid / F;
            constexpr int KPER2 = (BK / 2) / (THREADS / F);
#pragma unroll
            for (int q = 0; q < KPER2; q++) {
                int k2 = kg * KPER2 + q;
                Bs2[n * SST + k2] = pack_half2(B[(size_t)(kc + 2 * k2) * F + n],
                                               B[(size_t)(kc + 2 * k2 + 1) * F + n]);
            }
        }
        __syncthreads();

#pragma unroll
        for (int ks = 0; ks < BK / 16; ks++) {
            int k2b = ks * 8 + (lane & 3);
            unsigned a[4][4], b[4][2];
            int r0 = warpM * 64 + (lane >> 2);
#pragma unroll
            for (int mf = 0; mf < 4; mf++) {
                int rr = r0 + mf * 16;
                a[mf][0] = As2[rr * SST + k2b];
                a[mf][1] = As2[(rr + 8) * SST + k2b];
                a[mf][2] = As2[rr * SST + k2b + 4];
                a[mf][3] = As2[(rr + 8) * SST + k2b + 4];
            }
            int c0 = warpN * 32 + (lane >> 2);
#pragma unroll
            for (int nf = 0; nf < 4; nf++) {
                b[nf][0] = Bs2[(c0 + nf * 8) * SST + k2b];
                b[nf][1] = Bs2[(c0 + nf * 8) * SST + k2b + 4];
            }
#pragma unroll
            for (int mf = 0; mf < 4; mf++)
#pragma unroll
                for (int nf = 0; nf < 4; nf++) mma_f16(acc[mf][nf], a[mf], b[nf]);
        }
        __syncthreads();
    }

    int cThr = warpN * 32 + (lane & 3) * 2;

    if constexpr (EPI == 3) {
        __shared__ float ss[128];
        if (tid < 128) ss[tid] = 0.f;
        __syncthreads();
#pragma unroll
        for (int mf = 0; mf < 4; mf++) {
#pragma unroll
            for (int half = 0; half < 2; half++) {
                int lr = warpM * 64 + mf * 16 + half * 8 + (lane >> 2);
                float q = 0.f;
#pragma unroll
                for (int nf = 0; nf < 4; nf++) {
                    int gc = cThr + nf * 8;
                    float v0 = acc[mf][nf][half * 2 + 0] + vec[gc];
                    float v1 = acc[mf][nf][half * 2 + 1] + vec[gc + 1];
                    acc[mf][nf][half * 2 + 0] = v0;
                    acc[mf][nf][half * 2 + 1] = v1;
                    q = fmaf(v0, v0, q);
                    q = fmaf(v1, v1, q);
                }
                atomicAdd(&ss[lr], q);
            }
        }
        __syncthreads();
#pragma unroll
        for (int mf = 0; mf < 4; mf++) {
#pragma unroll
            for (int half = 0; half < 2; half++) {
                int lr = warpM * 64 + mf * 16 + half * 8 + (lane >> 2);
                int gr = rowBase + lr;
                if (gr >= nRows) continue;
                float nrm = sqrtf(ss[lr]);
                float inv = 1.0f / fmaxf(nrm, 1e-12f);
#pragma unroll
                for (int nf = 0; nf < 4; nf++) {
                    int gc = cThr + nf * 8;
                    *reinterpret_cast<float2*>(&((float*)C)[(size_t)gr * F + gc]) =
                        make_float2(acc[mf][nf][half * 2 + 0] * inv,
                                    acc[mf][nf][half * 2 + 1] * inv);
                }
            }
        }
    } else {
#pragma unroll
        for (int mf = 0; mf < 4; mf++) {
#pragma unroll
            for (int half = 0; half < 2; half++) {
                int gr = rowBase + warpM * 64 + mf * 16 + half * 8 + (lane >> 2);
                if (gr >= nRows) continue;
#pragma unroll
                for (int nf = 0; nf < 4; nf++) {
                    int gc = cThr + nf * 8;
                    float v0 = acc[mf][nf][half * 2 + 0];
                    float v1 = acc[mf][nf][half * 2 + 1];
                    if constexpr (sizeof(CT) == 4)
                        *reinterpret_cast<float2*>(&((float*)C)[(size_t)gr * F + gc]) =
                            make_float2(v0, v1);
                    else
                        *reinterpret_cast<__half2*>(&((__half*)C)[(size_t)gr * F + gc]) =
                            __floats2half2_rn(v0, v1);
                }
            }
        }
    }
}

template <int K, int F, int EPI, int LDA, typename AT, typename CT>
__global__ void gemm_tc(const AT* __restrict__ A, const float* __restrict__ B,
                        const float* __restrict__ vec, CT* __restrict__ C,
                        int nRows) {
    gemm_block<K, F, EPI, LDA, AT, CT>(A, B, vec, C, blockIdx.x * 128, nRows);
}

template <int K, int F, int EPI, int LDA>
__global__ void gemm_tc_dual(const float* __restrict__ A0, const float* __restrict__ A1,
                             const float* __restrict__ B, const float* __restrict__ vec,
                             __half* __restrict__ C, int N) {
    int g = blockIdx.y;
    const float* A = g ? A1 : A0;
    __half* Cg = C + (size_t)g * N * F;
    gemm_block<K, F, EPI, LDA, float, __half>(A, B, vec, Cg, blockIdx.x * 128, N);
}

// ---------------- projector GEMM + fused cluster head ------------------------
// H = relu(Z @ [Wp1|Wc1] + [bp1|bc1]); P (cols 0..63) -> Pout (row stride 128);
// Hc (cols 64..127) reduced against Wc2 in registers -> softmax -> outC.
// Hc is never written to memory.
__global__ __launch_bounds__(256) void proj_cluster_kernel(
    const __half* __restrict__ Z, __half* __restrict__ Pout,
    const float* __restrict__ Wc2, const float* __restrict__ bc2,
    float* __restrict__ outC, int nRows) {
    constexpr int SST = 20;
    __shared__ unsigned As2[128 * SST];
    __shared__ unsigned Bs2[128 * SST];
    __shared__ float slog[128 * 3];

    int tid = threadIdx.x;
    int lane = tid & 31;
    int warp = tid >> 5;
    int warpM = warp >> 2;    // 0..1
    int warpN = warp & 3;     // 0..3
    int rowBase = blockIdx.x * 128;

    for (int i = tid; i < 384; i += 256) slog[i] = 0.f;

    float acc[4][4][4];
#pragma unroll
    for (int i = 0; i < 4; i++)
#pragma unroll
        for (int j = 0; j < 4; j++)
#pragma unroll
            for (int q = 0; q < 4; q++) acc[i][j][q] = 0.0f;

    for (int kc = 0; kc < 64; kc += 32) {
#pragma unroll
        for (int q = 0; q < 4; q++) {
            int lin = tid + q * 256;
            int r = lin >> 3;
            int k4 = lin & 7;
            unsigned p0 = 0, p1 = 0;
            int gr = rowBase + r;
            if (gr < nRows) {
                uint2 v = *reinterpret_cast<const uint2*>(&Z[(size_t)gr * 64 + kc + k4 * 4]);
                p0 = v.x; p1 = v.y;
            }
            As2[r * SST + k4 * 2 + 0] = p0;
            As2[r * SST + k4 * 2 + 1] = p1;
        }
        {
            int n = tid & 127;
            int kg = tid >> 7;
#pragma unroll
            for (int q = 0; q < 8; q++) {
                int k2 = kg * 8 + q;
                Bs2[n * SST + k2] = pack_half2(g_wcomb[(size_t)(kc + 2 * k2) * 128 + n],
                                               g_wcomb[(size_t)(kc + 2 * k2 + 1) * 128 + n]);
            }
        }
        __syncthreads();
#pragma unroll
        for (int ks = 0; ks < 2; ks++) {
            int k2b = ks * 8 + (lane & 3);
            unsigned a[4][4], b[4][2];
            int r0 = warpM * 64 + (lane >> 2);
#pragma unroll
            for (int mf = 0; mf < 4; mf++) {
                int rr = r0 + mf * 16;
                a[mf][0] = As2[rr * SST + k2b];
                a[mf][1] = As2[(rr + 8) * SST + k2b];
                a[mf][2] = As2[rr * SST + k2b + 4];
                a[mf][3] = As2[(rr + 8) * SST + k2b + 4];
            }
            int c0 = warpN * 32 + (lane >> 2);
#pragma unroll
            for (int nf = 0; nf < 4; nf++) {
                b[nf][0] = Bs2[(c0 + nf * 8) * SST + k2b];
                b[nf][1] = Bs2[(c0 + nf * 8) * SST + k2b + 4];
            }
#pragma unroll
            for (int mf = 0; mf < 4; mf++)
#pragma unroll
                for (int nf = 0; nf < 4; nf++) mma_f16(acc[mf][nf], a[mf], b[nf]);
        }
        __syncthreads();
    }

    int cThr = warpN * 32 + (lane & 3) * 2;
#pragma unroll
    for (int mf = 0; mf < 4; mf++) {
#pragma unroll
        for (int half = 0; half < 2; half++) {
            int lr = warpM * 64 + mf * 16 + half * 8 + (lane >> 2);
            int gr = rowBase + lr;
            float l0 = 0.f, l1 = 0.f, l2 = 0.f;
#pragma unroll
            for (int nf = 0; nf < 4; nf++) {
                int gc = cThr + nf * 8;
                float v0 = fmaxf(acc[mf][nf][half * 2 + 0] + g_bcomb[gc], 0.f);
                float v1 = fmaxf(acc[mf][nf][half * 2 + 1] + g_bcomb[gc + 1], 0.f);
                if (warpN < 2) {
                    if (gr < nRows)
                        *reinterpret_cast<__half2*>(&Pout[(size_t)gr * 128 + gc]) =
                            __floats2half2_rn(v0, v1);
                } else {
                    int h = gc - 64;
                    l0 += v0 * Wc2[h * 3 + 0] + v1 * Wc2[(h + 1) * 3 + 0];
                    l1 += v0 * Wc2[h * 3 + 1] + v1 * Wc2[(h + 1) * 3 + 1];
                    l2 += v0 * Wc2[h * 3 + 2] + v1 * Wc2[(h + 1) * 3 + 2];
                }
            }
            if (warpN >= 2) {
                atomicAdd(&slog[lr * 3 + 0], l0);
                atomicAdd(&slog[lr * 3 + 1], l1);
                atomicAdd(&slog[lr * 3 + 2], l2);
            }
        }
    }
    __syncthreads();

    if (tid < 128) {
        int gr = rowBase + tid;
        if (gr < nRows) {
            float d0 = slog[tid * 3 + 0] + bc2[0];
            float d1 = slog[tid * 3 + 1] + bc2[1];
            float d2 = slog[tid * 3 + 2] + bc2[2];
            float m = fmaxf(d0, fmaxf(d1, d2));
            float e0 = __expf(d0 - m), e1 = __expf(d1 - m), e2 = __expf(d2 - m);
            float inv = 1.0f / (e0 + e1 + e2);
            outC[(size_t)gr * 3 + 0] = e0 * inv;
            outC[(size_t)gr * 3 + 1] = e1 * inv;
            outC[(size_t)gr * 3 + 2] = e2 * inv;
        }
    }
}

// ---------------- launch -----------------------------------------------------
extern "C" void kernel_launch(void* const* d_in, const int* in_sizes, int n_in,
                              void* d_out, int out_size) {
    const float* x1  = (const float*)d_in[0];
    const int*   ei1 = (const int*)  d_in[1];
    const float* x2  = (const float*)d_in[2];
    const int*   ei2 = (const int*)  d_in[3];
    const float* W1  = (const float*)d_in[4];
    const float* b1  = (const float*)d_in[5];
    const float* W2  = (const float*)d_in[6];
    const float* b2  = (const float*)d_in[7];
    const float* Wp1 = (const float*)d_in[8];
    const float* bp1 = (const float*)d_in[9];
    const float* Wp2 = (const float*)d_in[10];
    const float* bp2 = (const float*)d_in[11];
    const float* Wc1 = (const float*)d_in[12];
    const float* bc1 = (const float*)d_in[13];
    const float* Wc2 = (const float*)d_in[14];
    const float* bc2 = (const float*)d_in[15];

    int N = in_sizes[0] / 128;
    int E = in_sizes[1] / 2;
    int N2 = 2 * N;
    int E2 = 2 * E;

    float* out = (float*)d_out;
    float* out_z = out;                       // z_i then z_j, contiguous
    float* out_c = out + (size_t)N2 * 128;    // c_i then c_j, contiguous

    void *pA, *pB, *pC;
    cudaGetSymbolAddress(&pA, g_bufA);
    cudaGetSymbolAddress(&pB, g_bufB);
    cudaGetSymbolAddress(&pC, g_bufC);
    __half* bufA = (__half*)pA;
    __half* bufB = (__half*)pB;
    __half* bufC = (__half*)pC;

    int gemmGridN  = (N + 127) / 128;
    int scanBlocks = (N2 + 1023) / 1024;
    int aggGridN   = (N + 7) / 8;

    // One-time side-stream resources (created on first, non-captured call)
    static cudaStream_t s2 = nullptr;
    static cudaEvent_t evFork = nullptr, evPre = nullptr;
    static cudaEvent_t evG1 = nullptr, evEnd = nullptr;
    if (s2 == nullptr) {
        cudaStreamCreateWithFlags(&s2, cudaStreamNonBlocking);
        cudaEventCreateWithFlags(&evFork, cudaEventDisableTiming);
        cudaEventCreateWithFlags(&evPre, cudaEventDisableTiming);
        cudaEventCreateWithFlags(&evG1, cudaEventDisableTiming);
        cudaEventCreateWithFlags(&evEnd, cudaEventDisableTiming);
    }

    // ---- fork: preprocessing chain on s2, overlapping GEMM-1 ----
    cudaEventRecord(evFork, 0);
    cudaStreamWaitEvent(s2, evFork, 0);

    zero_pre_kernel<<<(N2 + 255) / 256, 256, 0, s2>>>(N2, Wp1, Wc1, bp1, bc1);
    hist_kernel<<<(E2 + 255) / 256, 256, 0, s2>>>(ei1, ei2, E, N);
    scan_blocks_kernel<<<scanBlocks, 1024, 0, s2>>>(N2);
    scan_top_kernel<<<1, 128, 0, s2>>>(scanBlocks, N2);
    scan_add_kernel<<<(N2 + 255) / 256, 256, 0, s2>>>(N2);
    fill_csr_kernel<<<(E2 + 255) / 256, 256, 0, s2>>>(ei1, ei2, E, N);
    cudaEventRecord(evPre, s2);

    // main stream: layer-1 GEMM for BOTH graphs (graph-independent)
    dim3 grid1(gemmGridN, 2);
    gemm_tc_dual<128, 128, 4, 128><<<grid1, 256>>>(x1, x2, W1, nullptr, bufA, N);
    cudaEventRecord(evG1, 0);

    // ---- per-graph chains on two streams ----
    cudaStreamWaitEvent(0, evPre, 0);
    cudaStreamWaitEvent(s2, evG1, 0);

    // graph-1 chain (rows [0, N))
    agg_warp_kernel<128><<<aggGridN, 256>>>(bufA, b1, bufB, 0, N);
    gemm_tc<128, 64, 4, 128, __half, __half><<<gemmGridN, 128>>>(bufB, W2, nullptr, bufA, N);
    agg_warp_kernel<64><<<aggGridN, 256>>>(bufA, b2, bufC, 0, N);
    proj_cluster_kernel<<<gemmGridN, 256>>>(bufC, bufB, Wc2, bc2, out_c, N);
    gemm_tc<64, 128, 3, 128, __half, float><<<gemmGridN, 256>>>(bufB, Wp2, bp2, out_z, N);

    // graph-2 chain (rows [N, 2N)) on s2
    agg_warp_kernel<128><<<aggGridN, 256, 0, s2>>>(bufA, b1, bufB, N, N2);
    gemm_tc<128, 64, 4, 128, __half, __half><<<gemmGridN, 128, 0, s2>>>(
        bufB + (size_t)N * 128, W2, nullptr, bufA + (size_t)N * 64, N);
    agg_warp_kernel<64><<<aggGridN, 256, 0, s2>>>(bufA, b2, bufC, N, N2);
    proj_cluster_kernel<<<gemmGridN, 256, 0, s2>>>(
        bufC + (size_t)N * 64, bufB + (size_t)N * 128, Wc2, bc2,
        out_c + (size_t)N * 3, N);
    gemm_tc<64, 128, 3, 128, __half, float><<<gemmGridN, 256, 0, s2>>>(
        bufB + (size_t)N * 128, Wp2, bp2, out_z + (size_t)N * 128, N);

    // ---- join ----
    cudaEventRecord(evEnd, s2);
    cudaStreamWaitEvent(0, evEnd, 0);
}

// round 16
// speedup vs baseline: 1.0407x; 1.0407x over previous
#include <cuda_runtime.h>
#include <cuda_fp16.h>
#include <math.h>

#define NMAX 50000
#define EMAX 800000
#define N2MAX (2 * NMAX)
#define E2MAX (2 * EMAX)

// ---------------- scratch (static device globals; no allocation) ------------
__device__ __half g_bufA[N2MAX * 128];   // GEMM outputs (pre-agg), fp16
__device__ __half g_bufB[N2MAX * 128];   // agg1 output / projector hidden, fp16
__device__ __half g_bufC[N2MAX * 64];    // encoder output Z, fp16
__device__ float  g_dinv[N2MAX];
__device__ int    g_deg[N2MAX];
__device__ int    g_off[N2MAX + 1];
__device__ int    g_rank[E2MAX];       // per-edge slot within target node
__device__ int    g_csr[E2MAX];
__device__ int    g_bsum[128];         // 64 entries per graph
__device__ int    g_bpre[128];
__device__ float  g_wcomb[64 * 128];   // [Wp1 | Wc1]
__device__ float  g_bcomb[128];        // [bp1 | bc1]

// ---------------- fp16 helpers ----------------------------------------------
__device__ __forceinline__ float4 ld_half4(const __half* p) {
    uint2 r = *reinterpret_cast<const uint2*>(p);
    __half2 h0 = *reinterpret_cast<__half2*>(&r.x);
    __half2 h1 = *reinterpret_cast<__half2*>(&r.y);
    float2 f0 = __half22float2(h0), f1 = __half22float2(h1);
    return make_float4(f0.x, f0.y, f1.x, f1.y);
}
__device__ __forceinline__ void st_half4(__half* p, float4 v) {
    __half2 h0 = __floats2half2_rn(v.x, v.y);
    __half2 h1 = __floats2half2_rn(v.z, v.w);
    uint2 r;
    r.x = *reinterpret_cast<unsigned*>(&h0);
    r.y = *reinterpret_cast<unsigned*>(&h1);
    *reinterpret_cast<uint2*>(p) = r;
}
__device__ __forceinline__ unsigned pack_half2(float a, float b) {
    __half2 h = __floats2half2_rn(a, b);
    return *reinterpret_cast<unsigned*>(&h);
}

// ---------------- per-graph preprocessing ------------------------------------
// zero graph-1 half + weight concat (runs on s2)
__global__ void zero_pre1_kernel(int n, const float* __restrict__ Wp1,
                                 const float* __restrict__ Wc1,
                                 const float* __restrict__ bp1,
                                 const float* __restrict__ bc1) {
    int i = blockIdx.x * blockDim.x + threadIdx.x;
    if (i < n) g_deg[i] = 0;
    if (i < 64 * 128) {
        int k = i >> 7, nn = i & 127;
        g_wcomb[i] = (nn < 64) ? Wp1[k * 64 + nn] : Wc1[k * 64 + nn - 64];
    }
    if (i < 128) g_bcomb[i] = (i < 64) ? bp1[i] : bc1[i - 64];
}

// zero graph-2 half (runs on s3)
__global__ void zero_pre2_kernel(int n, int nodeBase) {
    int i = blockIdx.x * blockDim.x + threadIdx.x;
    if (i < n) g_deg[nodeBase + i] = 0;
}

// Histogram + per-edge rank (one graph)
__global__ void hist_g_kernel(const int* __restrict__ ei, int E,
                              int nodeBase, int rankBase) {
    int i = blockIdx.x * blockDim.x + threadIdx.x;
    if (i >= E) return;
    int c = ei[E + i];
    g_rank[rankBase + i] = atomicAdd(&g_deg[nodeBase + c], 1);
}

// Per-1024-block scan of one graph's degrees; g_off gets ebase + local excl.
__global__ void scan_blocks_g_kernel(int n, int nodeBase, int ebase, int sbase) {
    int b = blockIdx.x, tid = threadIdx.x;
    int i = b * 1024 + tid;
    int lane = tid & 31, w = tid >> 5;
    int v = (i < n) ? g_deg[nodeBase + i] : 0;
    int s = v;
#pragma unroll
    for (int o = 1; o < 32; o <<= 1) {
        int t = __shfl_up_sync(0xffffffffu, s, o);
        if (lane >= o) s += t;
    }
    __shared__ int wsum[32];
    if (lane == 31) wsum[w] = s;
    __syncthreads();
    if (w == 0) {
        int t = wsum[lane];
#pragma unroll
        for (int o = 1; o < 32; o <<= 1) {
            int u = __shfl_up_sync(0xffffffffu, t, o);
            if (lane >= o) t += u;
        }
        wsum[lane] = t;
    }
    __syncthreads();
    int excl = s - v + (w > 0 ? wsum[w - 1] : 0);
    if (i < n) {
        g_off[nodeBase + i] = ebase + excl;
        g_dinv[nodeBase + i] = rsqrtf((float)(v + 1));
    }
    if (tid == 0) g_bsum[sbase + b] = wsum[31];
}

// Scan one graph's block totals (nb <= 64); writes end sentinel.
__global__ void scan_top_g_kernel(int nb, int n, int nodeBase, int ebase, int sbase) {
    int tid = threadIdx.x;   // 64
    __shared__ int sh[64];
    int v = (tid < nb) ? g_bsum[sbase + tid] : 0;
    sh[tid] = v;
    __syncthreads();
#pragma unroll
    for (int d = 1; d < 64; d <<= 1) {
        int t = (tid >= d) ? sh[tid - d] : 0;
        __syncthreads();
        sh[tid] += t;
        __syncthreads();
    }
    if (tid < nb) g_bpre[sbase + tid] = sh[tid] - v;
    if (tid == 63) g_off[nodeBase + n] = ebase + sh[63];
}

__global__ void scan_add_g_kernel(int n, int nodeBase, int sbase) {
    int i = blockIdx.x * blockDim.x + threadIdx.x;
    if (i < n) g_off[nodeBase + i] += g_bpre[sbase + (i >> 10)];
}

// Atomic-free CSR fill for one graph
__global__ void fill_g_kernel(const int* __restrict__ ei, int E,
                              int nodeBase, int rankBase) {
    int i = blockIdx.x * blockDim.x + threadIdx.x;
    if (i >= E) return;
    int r = ei[i];
    int c = ei[E + i];
    g_csr[g_off[nodeBase + c] + g_rank[rankBase + i]] = nodeBase + r;
}

// ---------------- neighbor aggregation: warp per node, fp16 rows --------------
// node range [base, nodeEnd). out[n] = relu(dinv[n]*(dinv[n]*G[n]+sum dj*G[j])+b)
template <int F>
__global__ void agg_warp_kernel(const __half* __restrict__ G,
                                const float* __restrict__ bias,
                                __half* __restrict__ out, int base, int nodeEnd) {
    int node = base + blockIdx.x * (blockDim.x >> 5) + (threadIdx.x >> 5);
    if (node >= nodeEnd) return;
    int lane = threadIdx.x & 31;
    int s = g_off[node], e = g_off[node + 1];
    float dn = g_dinv[node];

    if constexpr (F == 128) {
        float4 self = ld_half4(&G[(size_t)node * F + lane * 4]);
        float4 acc = make_float4(dn * self.x, dn * self.y, dn * self.z, dn * self.w);
        int j = s;
        for (; j + 4 <= e; j += 4) {
            int n0 = g_csr[j], n1 = g_csr[j + 1], n2 = g_csr[j + 2], n3 = g_csr[j + 3];
            float d0 = g_dinv[n0], d1 = g_dinv[n1], d2 = g_dinv[n2], d3 = g_dinv[n3];
            float4 v0 = ld_half4(&G[(size_t)n0 * F + lane * 4]);
            float4 v1 = ld_half4(&G[(size_t)n1 * F + lane * 4]);
            float4 v2 = ld_half4(&G[(size_t)n2 * F + lane * 4]);
            float4 v3 = ld_half4(&G[(size_t)n3 * F + lane * 4]);
            acc.x += d0 * v0.x + d1 * v1.x + d2 * v2.x + d3 * v3.x;
            acc.y += d0 * v0.y + d1 * v1.y + d2 * v2.y + d3 * v3.y;
            acc.z += d0 * v0.z + d1 * v1.z + d2 * v2.z + d3 * v3.z;
            acc.w += d0 * v0.w + d1 * v1.w + d2 * v2.w + d3 * v3.w;
        }
        for (; j < e; j++) {
            int nj = g_csr[j];
            float dj = g_dinv[nj];
            float4 v = ld_half4(&G[(size_t)nj * F + lane * 4]);
            acc.x = fmaf(dj, v.x, acc.x); acc.y = fmaf(dj, v.y, acc.y);
            acc.z = fmaf(dj, v.z, acc.z); acc.w = fmaf(dj, v.w, acc.w);
        }
        float4 bb = *reinterpret_cast<const float4*>(&bias[lane * 4]);
        float4 o;
        o.x = fmaxf(fmaf(dn, acc.x, bb.x), 0.f);
        o.y = fmaxf(fmaf(dn, acc.y, bb.y), 0.f);
        o.z = fmaxf(fmaf(dn, acc.z, bb.z), 0.f);
        o.w = fmaxf(fmaf(dn, acc.w, bb.w), 0.f);
        st_half4(&out[(size_t)node * F + lane * 4], o);
    } else {
        float2 self = __half22float2(*reinterpret_cast<const __half2*>(&G[(size_t)node * F + lane * 2]));
        float2 acc = make_float2(dn * self.x, dn * self.y);
        int j = s;
        for (; j + 4 <= e; j += 4) {
            int n0 = g_csr[j], n1 = g_csr[j + 1], n2 = g_csr[j + 2], n3 = g_csr[j + 3];
            float d0 = g_dinv[n0], d1 = g_dinv[n1], d2 = g_dinv[n2], d3 = g_dinv[n3];
            float2 v0 = __half22float2(*reinterpret_cast<const __half2*>(&G[(size_t)n0 * F + lane * 2]));
            float2 v1 = __half22float2(*reinterpret_cast<const __half2*>(&G[(size_t)n1 * F + lane * 2]));
            float2 v2 = __half22float2(*reinterpret_cast<const __half2*>(&G[(size_t)n2 * F + lane * 2]));
            float2 v3 = __half22float2(*reinterpret_cast<const __half2*>(&G[(size_t)n3 * F + lane * 2]));
            acc.x += d0 * v0.x + d1 * v1.x + d2 * v2.x + d3 * v3.x;
            acc.y += d0 * v0.y + d1 * v1.y + d2 * v2.y + d3 * v3.y;
        }
        for (; j < e; j++) {
            int nj = g_csr[j];
            float dj = g_dinv[nj];
            float2 v = __half22float2(*reinterpret_cast<const __half2*>(&G[(size_t)nj * F + lane * 2]));
            acc.x = fmaf(dj, v.x, acc.x); acc.y = fmaf(dj, v.y, acc.y);
        }
        float2 bb = *reinterpret_cast<const float2*>(&bias[lane * 2]);
        float ox = fmaxf(fmaf(dn, acc.x, bb.x), 0.f);
        float oy = fmaxf(fmaf(dn, acc.y, bb.y), 0.f);
        *reinterpret_cast<__half2*>(&out[(size_t)node * F + lane * 2]) =
            __floats2half2_rn(ox, oy);
    }
}

// ---------------- FP16 tensor-core GEMM (m16n8k16, fp32 accumulate) ----------
__device__ __forceinline__ void mma_f16(float c[4], const unsigned a[4],
                                        const unsigned b[2]) {
    asm volatile(
        "mma.sync.aligned.m16n8k16.row.col.f32.f16.f16.f32 "
        "{%0,%1,%2,%3}, {%4,%5,%6,%7}, {%8,%9}, {%0,%1,%2,%3};"
        : "+f"(c[0]), "+f"(c[1]), "+f"(c[2]), "+f"(c[3])
        : "r"(a[0]), "r"(a[1]), "r"(a[2]), "r"(a[3]), "r"(b[0]), "r"(b[1]));
}

// Proven round-10 GEMM core.
// EPI 1: out = relu(acc + vec[col])
// EPI 3: out = l2norm_row(acc + vec[col])   (F==128, CT=float)
// EPI 4: out = acc (raw store)
template <int K, int F, int EPI, int LDA, typename AT, typename CT>
__device__ __forceinline__ void gemm_block(
    const AT* __restrict__ A, const float* __restrict__ B,
    const float* __restrict__ vec, CT* __restrict__ C,
    int rowBase, int nRows) {
    constexpr int BK = 32;
    constexpr int SST = 20;
    constexpr int WN = F / 32;
    constexpr int THREADS = 32 * 2 * WN;
    __shared__ unsigned As2[128 * SST];
    __shared__ unsigned Bs2[F * SST];

    int tid = threadIdx.x;
    int lane = tid & 31;
    int warp = tid >> 5;
    int warpM = warp / WN;
    int warpN = warp % WN;

    float acc[4][4][4];
#pragma unroll
    for (int i = 0; i < 4; i++)
#pragma unroll
        for (int j = 0; j < 4; j++)
#pragma unroll
            for (int q = 0; q < 4; q++) acc[i][j][q] = 0.0f;

    for (int kc = 0; kc < K; kc += BK) {
        constexpr int AQ = (128 * BK / 4) / THREADS;
#pragma unroll
        for (int q = 0; q < AQ; q++) {
            int lin = tid + q * THREADS;
            int r = lin >> 3;
            int k4 = lin & 7;
            unsigned p0 = 0, p1 = 0;
            int gr = rowBase + r;
            if (gr < nRows) {
                if constexpr (sizeof(AT) == 4) {
                    float4 v = *reinterpret_cast<const float4*>(
                        &A[(size_t)gr * LDA + kc + k4 * 4]);
                    p0 = pack_half2(v.x, v.y);
                    p1 = pack_half2(v.z, v.w);
                } else {
                    uint2 v = *reinterpret_cast<const uint2*>(
                        &A[(size_t)gr * LDA + kc + k4 * 4]);
                    p0 = v.x; p1 = v.y;
                }
            }
            As2[r * SST + k4 * 2 + 0] = p0;
            As2[r * SST + k4 * 2 + 1] = p1;
        }
        {
            int n = tid % F;
            int kg = tid / F;
            constexpr int KPER2 = (BK / 2) / (THREADS / F);
#pragma unroll
            for (int q = 0; q < KPER2; q++) {
                int k2 = kg * KPER2 + q;
                Bs2[n * SST + k2] = pack_half2(B[(size_t)(kc + 2 * k2) * F + n],
                                               B[(size_t)(kc + 2 * k2 + 1) * F + n]);
            }
        }
        __syncthreads();

#pragma unroll
        for (int ks = 0; ks < BK / 16; ks++) {
            int k2b = ks * 8 + (lane & 3);
            unsigned a[4][4], b[4][2];
            int r0 = warpM * 64 + (lane >> 2);
#pragma unroll
            for (int mf = 0; mf < 4; mf++) {
                int rr = r0 + mf * 16;
                a[mf][0] = As2[rr * SST + k2b];
                a[mf][1] = As2[(rr + 8) * SST + k2b];
                a[mf][2] = As2[rr * SST + k2b + 4];
                a[mf][3] = As2[(rr + 8) * SST + k2b + 4];
            }
            int c0 = warpN * 32 + (lane >> 2);
#pragma unroll
            for (int nf = 0; nf < 4; nf++) {
                b[nf][0] = Bs2[(c0 + nf * 8) * SST + k2b];
                b[nf][1] = Bs2[(c0 + nf * 8) * SST + k2b + 4];
            }
#pragma unroll
            for (int mf = 0; mf < 4; mf++)
#pragma unroll
                for (int nf = 0; nf < 4; nf++) mma_f16(acc[mf][nf], a[mf], b[nf]);
        }
        __syncthreads();
    }

    int cThr = warpN * 32 + (lane & 3) * 2;

    if constexpr (EPI == 3) {
        __shared__ float ss[128];
        if (tid < 128) ss[tid] = 0.f;
        __syncthreads();
#pragma unroll
        for (int mf = 0; mf < 4; mf++) {
#pragma unroll
            for (int half = 0; half < 2; half++) {
                int lr = warpM * 64 + mf * 16 + half * 8 + (lane >> 2);
                float q = 0.f;
#pragma unroll
                for (int nf = 0; nf < 4; nf++) {
                    int gc = cThr + nf * 8;
                    float v0 = acc[mf][nf][half * 2 + 0] + vec[gc];
                    float v1 = acc[mf][nf][half * 2 + 1] + vec[gc + 1];
                    acc[mf][nf][half * 2 + 0] = v0;
                    acc[mf][nf][half * 2 + 1] = v1;
                    q = fmaf(v0, v0, q);
                    q = fmaf(v1, v1, q);
                }
                atomicAdd(&ss[lr], q);
            }
        }
        __syncthreads();
#pragma unroll
        for (int mf = 0; mf < 4; mf++) {
#pragma unroll
            for (int half = 0; half < 2; half++) {
                int lr = warpM * 64 + mf * 16 + half * 8 + (lane >> 2);
                int gr = rowBase + lr;
                if (gr >= nRows) continue;
                float nrm = sqrtf(ss[lr]);
                float inv = 1.0f / fmaxf(nrm, 1e-12f);
#pragma unroll
                for (int nf = 0; nf < 4; nf++) {
                    int gc = cThr + nf * 8;
                    *reinterpret_cast<float2*>(&((float*)C)[(size_t)gr * F + gc]) =
                        make_float2(acc[mf][nf][half * 2 + 0] * inv,
                                    acc[mf][nf][half * 2 + 1] * inv);
                }
            }
        }
    } else {
#pragma unroll
        for (int mf = 0; mf < 4; mf++) {
#pragma unroll
            for (int half = 0; half < 2; half++) {
                int gr = rowBase + warpM * 64 + mf * 16 + half * 8 + (lane >> 2);
                if (gr >= nRows) continue;
#pragma unroll
                for (int nf = 0; nf < 4; nf++) {
                    int gc = cThr + nf * 8;
                    float v0 = acc[mf][nf][half * 2 + 0];
                    float v1 = acc[mf][nf][half * 2 + 1];
                    if (EPI == 1) {
                        v0 = fmaxf(v0 + vec[gc], 0.f);
                        v1 = fmaxf(v1 + vec[gc + 1], 0.f);
                    }
                    if constexpr (sizeof(CT) == 4)
                        *reinterpret_cast<float2*>(&((float*)C)[(size_t)gr * F + gc]) =
                            make_float2(v0, v1);
                    else
                        *reinterpret_cast<__half2*>(&((__half*)C)[(size_t)gr * F + gc]) =
                            __floats2half2_rn(v0, v1);
                }
            }
        }
    }
}

template <int K, int F, int EPI, int LDA, typename AT, typename CT>
__global__ void gemm_tc(const AT* __restrict__ A, const float* __restrict__ B,
                        const float* __restrict__ vec, CT* __restrict__ C,
                        int nRows) {
    gemm_block<K, F, EPI, LDA, AT, CT>(A, B, vec, C, blockIdx.x * 128, nRows);
}

template <int K, int F, int EPI, int LDA>
__global__ void gemm_tc_dual(const float* __restrict__ A0, const float* __restrict__ A1,
                             const float* __restrict__ B, const float* __restrict__ vec,
                             __half* __restrict__ C, int N) {
    int g = blockIdx.y;
    const float* A = g ? A1 : A0;
    __half* Cg = C + (size_t)g * N * F;
    gemm_block<K, F, EPI, LDA, float, __half>(A, B, vec, Cg, blockIdx.x * 128, N);
}

// ---------------- fused cluster head: softmax((Hc@Wc2)+bc2) ------------------
// node range [base, nodeEnd); Hc rows at H + node*128 + 64
__global__ void cluster_kernel(const __half* __restrict__ H,
                               const float* __restrict__ Wc2,
                               const float* __restrict__ bc2,
                               float* __restrict__ out, int base, int nodeEnd) {
    int gtid = blockIdx.x * blockDim.x + threadIdx.x;
    int node = base + (gtid >> 5);
    int lane = gtid & 31;
    if (node >= nodeEnd) return;
    const __half* rowp = H + (size_t)node * 128 + 64;
    float2 v = __half22float2(*reinterpret_cast<const __half2*>(&rowp[lane * 2]));
    int k0 = lane * 2;
    float d0 = v.x * Wc2[k0 * 3 + 0] + v.y * Wc2[(k0 + 1) * 3 + 0];
    float d1 = v.x * Wc2[k0 * 3 + 1] + v.y * Wc2[(k0 + 1) * 3 + 1];
    float d2 = v.x * Wc2[k0 * 3 + 2] + v.y * Wc2[(k0 + 1) * 3 + 2];
#pragma unroll
    for (int o = 16; o > 0; o >>= 1) {
        d0 += __shfl_down_sync(0xffffffffu, d0, o);
        d1 += __shfl_down_sync(0xffffffffu, d1, o);
        d2 += __shfl_down_sync(0xffffffffu, d2, o);
    }
    if (lane == 0) {
        d0 += bc2[0]; d1 += bc2[1]; d2 += bc2[2];
        float m = fmaxf(d0, fmaxf(d1, d2));
        float e0 = __expf(d0 - m), e1 = __expf(d1 - m), e2 = __expf(d2 - m);
        float inv = 1.0f / (e0 + e1 + e2);
        out[(size_t)node * 3 + 0] = e0 * inv;
        out[(size_t)node * 3 + 1] = e1 * inv;
        out[(size_t)node * 3 + 2] = e2 * inv;
    }
}

// ---------------- launch -----------------------------------------------------
extern "C" void kernel_launch(void* const* d_in, const int* in_sizes, int n_in,
                              void* d_out, int out_size) {
    const float* x1  = (const float*)d_in[0];
    const int*   ei1 = (const int*)  d_in[1];
    const float* x2  = (const float*)d_in[2];
    const int*   ei2 = (const int*)  d_in[3];
    const float* W1  = (const float*)d_in[4];
    const float* b1  = (const float*)d_in[5];
    const float* W2  = (const float*)d_in[6];
    const float* b2  = (const float*)d_in[7];
    const float* Wp1 = (const float*)d_in[8];
    const float* bp1 = (const float*)d_in[9];
    const float* Wp2 = (const float*)d_in[10];
    const float* bp2 = (const float*)d_in[11];
    const float* Wc1 = (const float*)d_in[12];
    const float* bc1 = (const float*)d_in[13];
    const float* Wc2 = (const float*)d_in[14];
    const float* bc2 = (const float*)d_in[15];

    int N = in_sizes[0] / 128;
    int E = in_sizes[1] / 2;
    int N2 = 2 * N;

    float* out = (float*)d_out;
    float* out_z = out;                       // z_i then z_j, contiguous
    float* out_c = out + (size_t)N2 * 128;    // c_i then c_j, contiguous

    void *pA, *pB, *pC, *pW, *pBi;
    cudaGetSymbolAddress(&pA, g_bufA);
    cudaGetSymbolAddress(&pB, g_bufB);
    cudaGetSymbolAddress(&pC, g_bufC);
    cudaGetSymbolAddress(&pW, g_wcomb);
    cudaGetSymbolAddress(&pBi, g_bcomb);
    __half* bufA = (__half*)pA;
    __half* bufB = (__half*)pB;
    __half* bufC = (__half*)pC;
    float* wcomb = (float*)pW;
    float* bcomb = (float*)pBi;

    int gemmGridN  = (N + 127) / 128;
    int scanBlocksG = (N + 1023) / 1024;   // per graph
    int aggGridN   = (N + 7) / 8;

    // One-time side-stream resources (created on first, non-captured call)
    static cudaStream_t s2 = nullptr, s3 = nullptr;
    static cudaEvent_t evFork = nullptr, evPre1 = nullptr, evPre2 = nullptr;
    static cudaEvent_t evG1 = nullptr, evEnd = nullptr;
    if (s2 == nullptr) {
        cudaStreamCreateWithFlags(&s2, cudaStreamNonBlocking);
        cudaStreamCreateWithFlags(&s3, cudaStreamNonBlocking);
        cudaEventCreateWithFlags(&evFork, cudaEventDisableTiming);
        cudaEventCreateWithFlags(&evPre1, cudaEventDisableTiming);
        cudaEventCreateWithFlags(&evPre2, cudaEventDisableTiming);
        cudaEventCreateWithFlags(&evG1, cudaEventDisableTiming);
        cudaEventCreateWithFlags(&evEnd, cudaEventDisableTiming);
    }

    // ---- fork ----
    cudaEventRecord(evFork, 0);
    cudaStreamWaitEvent(s2, evFork, 0);
    cudaStreamWaitEvent(s3, evFork, 0);

    // s2: graph-1 preprocessing (+ weight concat)
    zero_pre1_kernel<<<(N + 255) / 256, 256, 0, s2>>>(N, Wp1, Wc1, bp1, bc1);
    hist_g_kernel<<<(E + 255) / 256, 256, 0, s2>>>(ei1, E, 0, 0);
    scan_blocks_g_kernel<<<scanBlocksG, 1024, 0, s2>>>(N, 0, 0, 0);
    scan_top_g_kernel<<<1, 64, 0, s2>>>(scanBlocksG, N, 0, 0, 0);
    scan_add_g_kernel<<<(N + 255) / 256, 256, 0, s2>>>(N, 0, 0);
    fill_g_kernel<<<(E + 255) / 256, 256, 0, s2>>>(ei1, E, 0, 0);
    cudaEventRecord(evPre1, s2);

    // s3: graph-2 preprocessing
    zero_pre2_kernel<<<(N + 255) / 256, 256, 0, s3>>>(N, N);
    hist_g_kernel<<<(E + 255) / 256, 256, 0, s3>>>(ei2, E, N, E);
    scan_blocks_g_kernel<<<scanBlocksG, 1024, 0, s3>>>(N, N, E, 64);
    scan_top_g_kernel<<<1, 64, 0, s3>>>(scanBlocksG, N, N, E, 64);
    scan_add_g_kernel<<<(N + 255) / 256, 256, 0, s3>>>(N, N, 64);
    fill_g_kernel<<<(E + 255) / 256, 256, 0, s3>>>(ei2, E, N, E);
    cudaEventRecord(evPre2, s3);

    // main stream: layer-1 GEMM for BOTH graphs (graph-independent)
    dim3 grid1(gemmGridN, 2);
    gemm_tc_dual<128, 128, 4, 128><<<grid1, 256>>>(x1, x2, W1, nullptr, bufA, N);
    cudaEventRecord(evG1, 0);

    // ---- per-graph chains on two streams ----
    cudaStreamWaitEvent(0, evPre1, 0);     // main: graph-1 chain needs graph-1 preproc
    cudaStreamWaitEvent(s2, evG1, 0);      // s2: graph-2 chain needs GEMM-1
    cudaStreamWaitEvent(s2, evPre2, 0);    //     and graph-2 preproc (from s3)

    // graph-1 chain (rows [0, N)) on main
    agg_warp_kernel<128><<<aggGridN, 256>>>(bufA, b1, bufB, 0, N);
    gemm_tc<128, 64, 4, 128, __half, __half><<<gemmGridN, 128>>>(bufB, W2, nullptr, bufA, N);
    agg_warp_kernel<64><<<aggGridN, 256>>>(bufA, b2, bufC, 0, N);
    gemm_tc<64, 128, 1, 64, __half, __half><<<gemmGridN, 256>>>(bufC, wcomb, bcomb, bufB, N);
    gemm_tc<64, 128, 3, 128, __half, float><<<gemmGridN, 256>>>(bufB, Wp2, bp2, out_z, N);
    cluster_kernel<<<((N * 32) + 255) / 256, 256>>>(bufB, Wc2, bc2, out_c, 0, N);

    // graph-2 chain (rows [N, 2N)) on s2
    agg_warp_kernel<128><<<aggGridN, 256, 0, s2>>>(bufA, b1, bufB, N, N2);
    gemm_tc<128, 64, 4, 128, __half, __half><<<gemmGridN, 128, 0, s2>>>(
        bufB + (size_t)N * 128, W2, nullptr, bufA + (size_t)N * 64, N);
    agg_warp_kernel<64><<<aggGridN, 256, 0, s2>>>(bufA, b2, bufC, N, N2);
    gemm_tc<64, 128, 1, 64, __half, __half><<<gemmGridN, 256, 0, s2>>>(
        bufC + (size_t)N * 64, wcomb, bcomb, bufB + (size_t)N * 128, N);
    gemm_tc<64, 128, 3, 128, __half, float><<<gemmGridN, 256, 0, s2>>>(
        bufB + (size_t)N * 128, Wp2, bp2, out_z + (size_t)N * 128, N);
    cluster_kernel<<<((N * 32) + 255) / 256, 256, 0, s2>>>(bufB, Wc2, bc2, out_c, N, N2);

    // ---- join ----
    cudaEventRecord(evEnd, s2);
    cudaStreamWaitEvent(0, evEnd, 0);
}

// round 17
// speedup vs baseline: 1.0510x; 1.0099x over previous
#include <cuda_runtime.h>
#include <cuda_fp16.h>
#include <math.h>

#define NMAX 50000
#define EMAX 800000
#define N2MAX (2 * NMAX)
#define E2MAX (2 * EMAX)

// ---------------- scratch (static device globals; no allocation) ------------
__device__ __half g_bufA[N2MAX * 128];   // GEMM outputs (pre-agg), fp16
__device__ __half g_bufB[N2MAX * 128];   // agg1 output / projector hidden, fp16
__device__ __half g_bufC[N2MAX * 64];    // encoder output Z, fp16
__device__ float  g_dinv[N2MAX];
__device__ int    g_deg[N2MAX];
__device__ int    g_off[N2MAX + 1];
__device__ int    g_rank[E2MAX];       // per-edge slot within target node
__device__ int    g_csr[E2MAX];
__device__ int    g_bsum[128];         // 64 entries per graph
__device__ int    g_bpre[128];
// pre-packed weights: Wpack[k2*F + n] = half2(W[2k2][n], W[2k2+1][n])
__device__ unsigned g_W1p[64 * 128];    // K=128, F=128
__device__ unsigned g_W2p[64 * 64];     // K=128, F=64
__device__ unsigned g_Wcombp[32 * 128]; // K=64,  F=128  ([Wp1|Wc1])
__device__ unsigned g_Wp2p[32 * 128];   // K=64,  F=128
__device__ float  g_bcomb[128];         // [bp1 | bc1]

// ---------------- fp16 helpers ----------------------------------------------
__device__ __forceinline__ float4 ld_half4(const __half* p) {
    uint2 r = *reinterpret_cast<const uint2*>(p);
    __half2 h0 = *reinterpret_cast<__half2*>(&r.x);
    __half2 h1 = *reinterpret_cast<__half2*>(&r.y);
    float2 f0 = __half22float2(h0), f1 = __half22float2(h1);
    return make_float4(f0.x, f0.y, f1.x, f1.y);
}
__device__ __forceinline__ void st_half4(__half* p, float4 v) {
    __half2 h0 = __floats2half2_rn(v.x, v.y);
    __half2 h1 = __floats2half2_rn(v.z, v.w);
    uint2 r;
    r.x = *reinterpret_cast<unsigned*>(&h0);
    r.y = *reinterpret_cast<unsigned*>(&h1);
    *reinterpret_cast<uint2*>(p) = r;
}
__device__ __forceinline__ unsigned pack_half2(float a, float b) {
    __half2 h = __floats2half2_rn(a, b);
    return *reinterpret_cast<unsigned*>(&h);
}

// ---------------- weight pre-pack (once per call, main stream head) ----------
// packs W1, W2, Wp2, and [Wp1|Wc1] into pair-packed fp16 operand layout.
__global__ void pack_weights_kernel(const float* __restrict__ W1,
                                    const float* __restrict__ W2,
                                    const float* __restrict__ Wp2,
                                    const float* __restrict__ Wp1,
                                    const float* __restrict__ Wc1,
                                    const float* __restrict__ bp1,
                                    const float* __restrict__ bc1) {
    int i = blockIdx.x * blockDim.x + threadIdx.x;
    // W1: 64 x 128
    if (i < 64 * 128) {
        int k2 = i >> 7, n = i & 127;
        g_W1p[i] = pack_half2(W1[(2 * k2) * 128 + n], W1[(2 * k2 + 1) * 128 + n]);
    }
    // W2: 64 x 64
    if (i < 64 * 64) {
        int k2 = i >> 6, n = i & 63;
        g_W2p[i] = pack_half2(W2[(2 * k2) * 64 + n], W2[(2 * k2 + 1) * 64 + n]);
    }
    // Wp2: 32 x 128
    if (i < 32 * 128) {
        int k2 = i >> 7, n = i & 127;
        g_Wp2p[i] = pack_half2(Wp2[(2 * k2) * 128 + n], Wp2[(2 * k2 + 1) * 128 + n]);
    }
    // Wcomb: 32 x 128 from [Wp1|Wc1]
    if (i < 32 * 128) {
        int k2 = i >> 7, n = i & 127;
        float a = (n < 64) ? Wp1[(2 * k2) * 64 + n]     : Wc1[(2 * k2) * 64 + n - 64];
        float b = (n < 64) ? Wp1[(2 * k2 + 1) * 64 + n] : Wc1[(2 * k2 + 1) * 64 + n - 64];
        g_Wcombp[i] = pack_half2(a, b);
    }
    if (i < 128) g_bcomb[i] = (i < 64) ? bp1[i] : bc1[i - 64];
}

// ---------------- per-graph preprocessing ------------------------------------
__global__ void zero_pre_g_kernel(int n, int nodeBase) {
    int i = blockIdx.x * blockDim.x + threadIdx.x;
    if (i < n) g_deg[nodeBase + i] = 0;
}

__global__ void hist_g_kernel(const int* __restrict__ ei, int E,
                              int nodeBase, int rankBase) {
    int i = blockIdx.x * blockDim.x + threadIdx.x;
    if (i >= E) return;
    int c = ei[E + i];
    g_rank[rankBase + i] = atomicAdd(&g_deg[nodeBase + c], 1);
}

__global__ void scan_blocks_g_kernel(int n, int nodeBase, int ebase, int sbase) {
    int b = blockIdx.x, tid = threadIdx.x;
    int i = b * 1024 + tid;
    int lane = tid & 31, w = tid >> 5;
    int v = (i < n) ? g_deg[nodeBase + i] : 0;
    int s = v;
#pragma unroll
    for (int o = 1; o < 32; o <<= 1) {
        int t = __shfl_up_sync(0xffffffffu, s, o);
        if (lane >= o) s += t;
    }
    __shared__ int wsum[32];
    if (lane == 31) wsum[w] = s;
    __syncthreads();
    if (w == 0) {
        int t = wsum[lane];
#pragma unroll
        for (int o = 1; o < 32; o <<= 1) {
            int u = __shfl_up_sync(0xffffffffu, t, o);
            if (lane >= o) t += u;
        }
        wsum[lane] = t;
    }
    __syncthreads();
    int excl = s - v + (w > 0 ? wsum[w - 1] : 0);
    if (i < n) {
        g_off[nodeBase + i] = ebase + excl;
        g_dinv[nodeBase + i] = rsqrtf((float)(v + 1));
    }
    if (tid == 0) g_bsum[sbase + b] = wsum[31];
}

__global__ void scan_top_g_kernel(int nb, int n, int nodeBase, int ebase, int sbase) {
    int tid = threadIdx.x;   // 64
    __shared__ int sh[64];
    int v = (tid < nb) ? g_bsum[sbase + tid] : 0;
    sh[tid] = v;
    __syncthreads();
#pragma unroll
    for (int d = 1; d < 64; d <<= 1) {
        int t = (tid >= d) ? sh[tid - d] : 0;
        __syncthreads();
        sh[tid] += t;
        __syncthreads();
    }
    if (tid < nb) g_bpre[sbase + tid] = sh[tid] - v;
    if (tid == 63) g_off[nodeBase + n] = ebase + sh[63];
}

__global__ void scan_add_g_kernel(int n, int nodeBase, int sbase) {
    int i = blockIdx.x * blockDim.x + threadIdx.x;
    if (i < n) g_off[nodeBase + i] += g_bpre[sbase + (i >> 10)];
}

__global__ void fill_g_kernel(const int* __restrict__ ei, int E,
                              int nodeBase, int rankBase) {
    int i = blockIdx.x * blockDim.x + threadIdx.x;
    if (i >= E) return;
    int r = ei[i];
    int c = ei[E + i];
    g_csr[g_off[nodeBase + c] + g_rank[rankBase + i]] = nodeBase + r;
}

// ---------------- neighbor aggregation: warp per node, fp16 rows --------------
template <int F>
__global__ void agg_warp_kernel(const __half* __restrict__ G,
                                const float* __restrict__ bias,
                                __half* __restrict__ out, int base, int nodeEnd) {
    int node = base + blockIdx.x * (blockDim.x >> 5) + (threadIdx.x >> 5);
    if (node >= nodeEnd) return;
    int lane = threadIdx.x & 31;
    int s = g_off[node], e = g_off[node + 1];
    float dn = g_dinv[node];

    if constexpr (F == 128) {
        float4 self = ld_half4(&G[(size_t)node * F + lane * 4]);
        float4 acc = make_float4(dn * self.x, dn * self.y, dn * self.z, dn * self.w);
        int j = s;
        for (; j + 4 <= e; j += 4) {
            int n0 = g_csr[j], n1 = g_csr[j + 1], n2 = g_csr[j + 2], n3 = g_csr[j + 3];
            float d0 = g_dinv[n0], d1 = g_dinv[n1], d2 = g_dinv[n2], d3 = g_dinv[n3];
            float4 v0 = ld_half4(&G[(size_t)n0 * F + lane * 4]);
            float4 v1 = ld_half4(&G[(size_t)n1 * F + lane * 4]);
            float4 v2 = ld_half4(&G[(size_t)n2 * F + lane * 4]);
            float4 v3 = ld_half4(&G[(size_t)n3 * F + lane * 4]);
            acc.x += d0 * v0.x + d1 * v1.x + d2 * v2.x + d3 * v3.x;
            acc.y += d0 * v0.y + d1 * v1.y + d2 * v2.y + d3 * v3.y;
            acc.z += d0 * v0.z + d1 * v1.z + d2 * v2.z + d3 * v3.z;
            acc.w += d0 * v0.w + d1 * v1.w + d2 * v2.w + d3 * v3.w;
        }
        for (; j < e; j++) {
            int nj = g_csr[j];
            float dj = g_dinv[nj];
            float4 v = ld_half4(&G[(size_t)nj * F + lane * 4]);
            acc.x = fmaf(dj, v.x, acc.x); acc.y = fmaf(dj, v.y, acc.y);
            acc.z = fmaf(dj, v.z, acc.z); acc.w = fmaf(dj, v.w, acc.w);
        }
        float4 bb = *reinterpret_cast<const float4*>(&bias[lane * 4]);
        float4 o;
        o.x = fmaxf(fmaf(dn, acc.x, bb.x), 0.f);
        o.y = fmaxf(fmaf(dn, acc.y, bb.y), 0.f);
        o.z = fmaxf(fmaf(dn, acc.z, bb.z), 0.f);
        o.w = fmaxf(fmaf(dn, acc.w, bb.w), 0.f);
        st_half4(&out[(size_t)node * F + lane * 4], o);
    } else {
        float2 self = __half22float2(*reinterpret_cast<const __half2*>(&G[(size_t)node * F + lane * 2]));
        float2 acc = make_float2(dn * self.x, dn * self.y);
        int j = s;
        for (; j + 4 <= e; j += 4) {
            int n0 = g_csr[j], n1 = g_csr[j + 1], n2 = g_csr[j + 2], n3 = g_csr[j + 3];
            float d0 = g_dinv[n0], d1 = g_dinv[n1], d2 = g_dinv[n2], d3 = g_dinv[n3];
            float2 v0 = __half22float2(*reinterpret_cast<const __half2*>(&G[(size_t)n0 * F + lane * 2]));
            float2 v1 = __half22float2(*reinterpret_cast<const __half2*>(&G[(size_t)n1 * F + lane * 2]));
            float2 v2 = __half22float2(*reinterpret_cast<const __half2*>(&G[(size_t)n2 * F + lane * 2]));
            float2 v3 = __half22float2(*reinterpret_cast<const __half2*>(&G[(size_t)n3 * F + lane * 2]));
            acc.x += d0 * v0.x + d1 * v1.x + d2 * v2.x + d3 * v3.x;
            acc.y += d0 * v0.y + d1 * v1.y + d2 * v2.y + d3 * v3.y;
        }
        for (; j < e; j++) {
            int nj = g_csr[j];
            float dj = g_dinv[nj];
            float2 v = __half22float2(*reinterpret_cast<const __half2*>(&G[(size_t)nj * F + lane * 2]));
            acc.x = fmaf(dj, v.x, acc.x); acc.y = fmaf(dj, v.y, acc.y);
        }
        float2 bb = *reinterpret_cast<const float2*>(&bias[lane * 2]);
        float ox = fmaxf(fmaf(dn, acc.x, bb.x), 0.f);
        float oy = fmaxf(fmaf(dn, acc.y, bb.y), 0.f);
        *reinterpret_cast<__half2*>(&out[(size_t)node * F + lane * 2]) =
            __floats2half2_rn(ox, oy);
    }
}

// ---------------- FP16 tensor-core GEMM (m16n8k16, fp32 accumulate) ----------
__device__ __forceinline__ void mma_f16(float c[4], const unsigned a[4],
                                        const unsigned b[2]) {
    asm volatile(
        "mma.sync.aligned.m16n8k16.row.col.f32.f16.f16.f32 "
        "{%0,%1,%2,%3}, {%4,%5,%6,%7}, {%8,%9}, {%0,%1,%2,%3};"
        : "+f"(c[0]), "+f"(c[1]), "+f"(c[2]), "+f"(c[3])
        : "r"(a[0]), "r"(a[1]), "r"(a[2]), "r"(a[3]), "r"(b[0]), "r"(b[1]));
}

// Proven GEMM core; B supplied pre-packed: Bp[k2*F + n] = half2(B[2k2][n], B[2k2+1][n]).
// EPI 1: out = relu(acc + vec[col])
// EPI 3: out = l2norm_row(acc + vec[col])   (F==128, CT=float)
// EPI 4: out = acc (raw store)
template <int K, int F, int EPI, int LDA, typename AT, typename CT>
__device__ __forceinline__ void gemm_block(
    const AT* __restrict__ A, const unsigned* __restrict__ Bp,
    const float* __restrict__ vec, CT* __restrict__ C,
    int rowBase, int nRows) {
    constexpr int BK = 32;
    constexpr int SST = 20;
    constexpr int WN = F / 32;
    constexpr int THREADS = 32 * 2 * WN;
    __shared__ unsigned As2[128 * SST];
    __shared__ unsigned Bs2[F * SST];

    int tid = threadIdx.x;
    int lane = tid & 31;
    int warp = tid >> 5;
    int warpM = warp / WN;
    int warpN = warp % WN;

    float acc[4][4][4];
#pragma unroll
    for (int i = 0; i < 4; i++)
#pragma unroll
        for (int j = 0; j < 4; j++)
#pragma unroll
            for (int q = 0; q < 4; q++) acc[i][j][q] = 0.0f;

    for (int kc = 0; kc < K; kc += BK) {
        constexpr int AQ = (128 * BK / 4) / THREADS;
#pragma unroll
        for (int q = 0; q < AQ; q++) {
            int lin = tid + q * THREADS;
            int r = lin >> 3;
            int k4 = lin & 7;
            unsigned p0 = 0, p1 = 0;
            int gr = rowBase + r;
            if (gr < nRows) {
                if constexpr (sizeof(AT) == 4) {
                    float4 v = *reinterpret_cast<const float4*>(
                        &A[(size_t)gr * LDA + kc + k4 * 4]);
                    p0 = pack_half2(v.x, v.y);
                    p1 = pack_half2(v.z, v.w);
                } else {
                    uint2 v = *reinterpret_cast<const uint2*>(
                        &A[(size_t)gr * LDA + kc + k4 * 4]);
                    p0 = v.x; p1 = v.y;
                }
            }
            As2[r * SST + k4 * 2 + 0] = p0;
            As2[r * SST + k4 * 2 + 1] = p1;
        }
        {
            int n = tid % F;
            int kg = tid / F;
            constexpr int KPER2 = (BK / 2) / (THREADS / F);
            int kc2 = kc >> 1;
#pragma unroll
            for (int q = 0; q < KPER2; q++) {
                int k2 = kg * KPER2 + q;
                Bs2[n * SST + k2] = Bp[(size_t)(kc2 + k2) * F + n];
            }
        }
        __syncthreads();

#pragma unroll
        for (int ks = 0; ks < BK / 16; ks++) {
            int k2b = ks * 8 + (lane & 3);
            unsigned a[4][4], b[4][2];
            int r0 = warpM * 64 + (lane >> 2);
#pragma unroll
            for (int mf = 0; mf < 4; mf++) {
                int rr = r0 + mf * 16;
                a[mf][0] = As2[rr * SST + k2b];
                a[mf][1] = As2[(rr + 8) * SST + k2b];
                a[mf][2] = As2[rr * SST + k2b + 4];
                a[mf][3] = As2[(rr + 8) * SST + k2b + 4];
            }
            int c0 = warpN * 32 + (lane >> 2);
#pragma unroll
            for (int nf = 0; nf < 4; nf++) {
                b[nf][0] = Bs2[(c0 + nf * 8) * SST + k2b];
                b[nf][1] = Bs2[(c0 + nf * 8) * SST + k2b + 4];
            }
#pragma unroll
            for (int mf = 0; mf < 4; mf++)
#pragma unroll
                for (int nf = 0; nf < 4; nf++) mma_f16(acc[mf][nf], a[mf], b[nf]);
        }
        __syncthreads();
    }

    int cThr = warpN * 32 + (lane & 3) * 2;

    if constexpr (EPI == 3) {
        __shared__ float ss[128];
        if (tid < 128) ss[tid] = 0.f;
        __syncthreads();
#pragma unroll
        for (int mf = 0; mf < 4; mf++) {
#pragma unroll
            for (int half = 0; half < 2; half++) {
                int lr = warpM * 64 + mf * 16 + half * 8 + (lane >> 2);
                float q = 0.f;
#pragma unroll
                for (int nf = 0; nf < 4; nf++) {
                    int gc = cThr + nf * 8;
                    float v0 = acc[mf][nf][half * 2 + 0] + vec[gc];
                    float v1 = acc[mf][nf][half * 2 + 1] + vec[gc + 1];
                    acc[mf][nf][half * 2 + 0] = v0;
                    acc[mf][nf][half * 2 + 1] = v1;
                    q = fmaf(v0, v0, q);
                    q = fmaf(v1, v1, q);
                }
                atomicAdd(&ss[lr], q);
            }
        }
        __syncthreads();
#pragma unroll
        for (int mf = 0; mf < 4; mf++) {
#pragma unroll
            for (int half = 0; half < 2; half++) {
                int lr = warpM * 64 + mf * 16 + half * 8 + (lane >> 2);
                int gr = rowBase + lr;
                if (gr >= nRows) continue;
                float nrm = sqrtf(ss[lr]);
                float inv = 1.0f / fmaxf(nrm, 1e-12f);
#pragma unroll
                for (int nf = 0; nf < 4; nf++) {
                    int gc = cThr + nf * 8;
                    *reinterpret_cast<float2*>(&((float*)C)[(size_t)gr * F + gc]) =
                        make_float2(acc[mf][nf][half * 2 + 0] * inv,
                                    acc[mf][nf][half * 2 + 1] * inv);
                }
            }
        }
    } else {
#pragma unroll
        for (int mf = 0; mf < 4; mf++) {
#pragma unroll
            for (int half = 0; half < 2; half++) {
                int gr = rowBase + warpM * 64 + mf * 16 + half * 8 + (lane >> 2);
                if (gr >= nRows) continue;
#pragma unroll
                for (int nf = 0; nf < 4; nf++) {
                    int gc = cThr + nf * 8;
                    float v0 = acc[mf][nf][half * 2 + 0];
                    float v1 = acc[mf][nf][half * 2 + 1];
                    if (EPI == 1) {
                        v0 = fmaxf(v0 + vec[gc], 0.f);
                        v1 = fmaxf(v1 + vec[gc + 1], 0.f);
                    }
                    if constexpr (sizeof(CT) == 4)
                        *reinterpret_cast<float2*>(&((float*)C)[(size_t)gr * F + gc]) =
                            make_float2(v0, v1);
                    else
                        *reinterpret_cast<__half2*>(&((__half*)C)[(size_t)gr * F + gc]) =
                            __floats2half2_rn(v0, v1);
                }
            }
        }
    }
}

template <int K, int F, int EPI, int LDA, typename AT, typename CT>
__global__ void gemm_tc(const AT* __restrict__ A, const unsigned* __restrict__ Bp,
                        const float* __restrict__ vec, CT* __restrict__ C,
                        int nRows) {
    gemm_block<K, F, EPI, LDA, AT, CT>(A, Bp, vec, C, blockIdx.x * 128, nRows);
}

template <int K, int F, int EPI, int LDA>
__global__ void gemm_tc_dual(const float* __restrict__ A0, const float* __restrict__ A1,
                             const unsigned* __restrict__ Bp,
                             const float* __restrict__ vec,
                             __half* __restrict__ C, int N) {
    int g = blockIdx.y;
    const float* A = g ? A1 : A0;
    __half* Cg = C + (size_t)g * N * F;
    gemm_block<K, F, EPI, LDA, float, __half>(A, Bp, vec, Cg, blockIdx.x * 128, N);
}

// ---------------- fused cluster head: softmax((Hc@Wc2)+bc2) ------------------
__global__ void cluster_kernel(const __half* __restrict__ H,
                               const float* __restrict__ Wc2,
                               const float* __restrict__ bc2,
                               float* __restrict__ out, int base, int nodeEnd) {
    int gtid = blockIdx.x * blockDim.x + threadIdx.x;
    int node = base + (gtid >> 5);
    int lane = gtid & 31;
    if (node >= nodeEnd) return;
    const __half* rowp = H + (size_t)node * 128 + 64;
    float2 v = __half22float2(*reinterpret_cast<const __half2*>(&rowp[lane * 2]));
    int k0 = lane * 2;
    float d0 = v.x * Wc2[k0 * 3 + 0] + v.y * Wc2[(k0 + 1) * 3 + 0];
    float d1 = v.x * Wc2[k0 * 3 + 1] + v.y * Wc2[(k0 + 1) * 3 + 1];
    float d2 = v.x * Wc2[k0 * 3 + 2] + v.y * Wc2[(k0 + 1) * 3 + 2];
#pragma unroll
    for (int o = 16; o > 0; o >>= 1) {
        d0 += __shfl_down_sync(0xffffffffu, d0, o);
        d1 += __shfl_down_sync(0xffffffffu, d1, o);
        d2 += __shfl_down_sync(0xffffffffu, d2, o);
    }
    if (lane == 0) {
        d0 += bc2[0]; d1 += bc2[1]; d2 += bc2[2];
        float m = fmaxf(d0, fmaxf(d1, d2));
        float e0 = __expf(d0 - m), e1 = __expf(d1 - m), e2 = __expf(d2 - m);
        float inv = 1.0f / (e0 + e1 + e2);
        out[(size_t)node * 3 + 0] = e0 * inv;
        out[(size_t)node * 3 + 1] = e1 * inv;
        out[(size_t)node * 3 + 2] = e2 * inv;
    }
}

// ---------------- launch -----------------------------------------------------
extern "C" void kernel_launch(void* const* d_in, const int* in_sizes, int n_in,
                              void* d_out, int out_size) {
    const float* x1  = (const float*)d_in[0];
    const int*   ei1 = (const int*)  d_in[1];
    const float* x2  = (const float*)d_in[2];
    const int*   ei2 = (const int*)  d_in[3];
    const float* W1  = (const float*)d_in[4];
    const float* b1  = (const float*)d_in[5];
    const float* W2  = (const float*)d_in[6];
    const float* b2  = (const float*)d_in[7];
    const float* Wp1 = (const float*)d_in[8];
    const float* bp1 = (const float*)d_in[9];
    const float* Wp2 = (const float*)d_in[10];
    const float* bp2 = (const float*)d_in[11];
    const float* Wc1 = (const float*)d_in[12];
    const float* bc1 = (const float*)d_in[13];
    const float* Wc2 = (const float*)d_in[14];
    const float* bc2 = (const float*)d_in[15];

    int N = in_sizes[0] / 128;
    int E = in_sizes[1] / 2;
    int N2 = 2 * N;

    float* out = (float*)d_out;
    float* out_z = out;                       // z_i then z_j, contiguous
    float* out_c = out + (size_t)N2 * 128;    // c_i then c_j, contiguous

    void *pA, *pB, *pC, *pW1, *pW2, *pWc, *pWp2, *pBi;
    cudaGetSymbolAddress(&pA, g_bufA);
    cudaGetSymbolAddress(&pB, g_bufB);
    cudaGetSymbolAddress(&pC, g_bufC);
    cudaGetSymbolAddress(&pW1, g_W1p);
    cudaGetSymbolAddress(&pW2, g_W2p);
    cudaGetSymbolAddress(&pWc, g_Wcombp);
    cudaGetSymbolAddress(&pWp2, g_Wp2p);
    cudaGetSymbolAddress(&pBi, g_bcomb);
    __half* bufA = (__half*)pA;
    __half* bufB = (__half*)pB;
    __half* bufC = (__half*)pC;
    unsigned* W1p = (unsigned*)pW1;
    unsigned* W2p = (unsigned*)pW2;
    unsigned* Wcombp = (unsigned*)pWc;
    unsigned* Wp2p = (unsigned*)pWp2;
    float* bcomb = (float*)pBi;

    int gemmGridN  = (N + 127) / 128;
    int scanBlocksG = (N + 1023) / 1024;   // per graph
    int aggGridN   = (N + 7) / 8;

    // One-time side-stream resources (created on first, non-captured call)
    static cudaStream_t s2 = nullptr, s3 = nullptr;
    static cudaEvent_t evFork = nullptr, evPre1 = nullptr, evPre2 = nullptr;
    static cudaEvent_t evG1 = nullptr, evEnd = nullptr;
    if (s2 == nullptr) {
        cudaStreamCreateWithFlags(&s2, cudaStreamNonBlocking);
        cudaStreamCreateWithFlags(&s3, cudaStreamNonBlocking);
        cudaEventCreateWithFlags(&evFork, cudaEventDisableTiming);
        cudaEventCreateWithFlags(&evPre1, cudaEventDisableTiming);
        cudaEventCreateWithFlags(&evPre2, cudaEventDisableTiming);
        cudaEventCreateWithFlags(&evG1, cudaEventDisableTiming);
        cudaEventCreateWithFlags(&evEnd, cudaEventDisableTiming);
    }

    // ---- fork ----
    cudaEventRecord(evFork, 0);
    cudaStreamWaitEvent(s2, evFork, 0);
    cudaStreamWaitEvent(s3, evFork, 0);

    // s2: graph-1 preprocessing
    zero_pre_g_kernel<<<(N + 255) / 256, 256, 0, s2>>>(N, 0);
    hist_g_kernel<<<(E + 255) / 256, 256, 0, s2>>>(ei1, E, 0, 0);
    scan_blocks_g_kernel<<<scanBlocksG, 1024, 0, s2>>>(N, 0, 0, 0);
    scan_top_g_kernel<<<1, 64, 0, s2>>>(scanBlocksG, N, 0, 0, 0);
    scan_add_g_kernel<<<(N + 255) / 256, 256, 0, s2>>>(N, 0, 0);
    fill_g_kernel<<<(E + 255) / 256, 256, 0, s2>>>(ei1, E, 0, 0);
    cudaEventRecord(evPre1, s2);

    // s3: graph-2 preprocessing
    zero_pre_g_kernel<<<(N + 255) / 256, 256, 0, s3>>>(N, N);
    hist_g_kernel<<<(E + 255) / 256, 256, 0, s3>>>(ei2, E, N, E);
    scan_blocks_g_kernel<<<scanBlocksG, 1024, 0, s3>>>(N, N, E, 64);
    scan_top_g_kernel<<<1, 64, 0, s3>>>(scanBlocksG, N, N, E, 64);
    scan_add_g_kernel<<<(N + 255) / 256, 256, 0, s3>>>(N, N, 64);
    fill_g_kernel<<<(E + 255) / 256, 256, 0, s3>>>(ei2, E, N, E);
    cudaEventRecord(evPre2, s3);

    // main stream: weight pre-pack, then layer-1 GEMM for BOTH graphs
    pack_weights_kernel<<<(64 * 128 + 255) / 256, 256>>>(W1, W2, Wp2, Wp1, Wc1,
                                                         bp1, bc1);
    dim3 grid1(gemmGridN, 2);
    gemm_tc_dual<128, 128, 4, 128><<<grid1, 256>>>(x1, x2, W1p, nullptr, bufA, N);
    cudaEventRecord(evG1, 0);

    // ---- per-graph chains on two streams ----
    cudaStreamWaitEvent(0, evPre1, 0);     // main: graph-1 chain needs graph-1 preproc
    cudaStreamWaitEvent(s2, evG1, 0);      // s2: graph-2 chain needs GEMM-1
    cudaStreamWaitEvent(s2, evPre2, 0);    //     and graph-2 preproc (from s3)

    // graph-1 chain (rows [0, N)) on main
    agg_warp_kernel<128><<<aggGridN, 256>>>(bufA, b1, bufB, 0, N);
    gemm_tc<128, 64, 4, 128, __half, __half><<<gemmGridN, 128>>>(bufB, W2p, nullptr, bufA, N);
    agg_warp_kernel<64><<<aggGridN, 256>>>(bufA, b2, bufC, 0, N);
    gemm_tc<64, 128, 1, 64, __half, __half><<<gemmGridN, 256>>>(bufC, Wcombp, bcomb, bufB, N);
    gemm_tc<64, 128, 3, 128, __half, float><<<gemmGridN, 256>>>(bufB, Wp2p, bp2, out_z, N);
    cluster_kernel<<<((N * 32) + 255) / 256, 256>>>(bufB, Wc2, bc2, out_c, 0, N);

    // graph-2 chain (rows [N, 2N)) on s2
    agg_warp_kernel<128><<<aggGridN, 256, 0, s2>>>(bufA, b1, bufB, N, N2);
    gemm_tc<128, 64, 4, 128, __half, __half><<<gemmGridN, 128, 0, s2>>>(
        bufB + (size_t)N * 128, W2p, nullptr, bufA + (size_t)N * 64, N);
    agg_warp_kernel<64><<<aggGridN, 256, 0, s2>>>(bufA, b2, bufC, N, N2);
    gemm_tc<64, 128, 1, 64, __half, __half><<<gemmGridN, 256, 0, s2>>>(
        bufC + (size_t)N * 64, Wcombp, bcomb, bufB + (size_t)N * 128, N);
    gemm_tc<64, 128, 3, 128, __half, float><<<gemmGridN, 256, 0, s2>>>(
        bufB + (size_t)N * 128, Wp2p, bp2, out_z + (size_t)N * 128, N);
    cluster_kernel<<<((N * 32) + 255) / 256, 256, 0, s2>>>(bufB, Wc2, bc2, out_c, N, N2);

    // ---- join ----
    cudaEventRecord(evEnd, s2);
    cudaStreamWaitEvent(0, evEnd, 0);
}